// round 15
// baseline (speedup 1.0000x reference)
#include <cuda_runtime.h>
#include <cuda_bf16.h>
#include <cstdint>
#include <cstddef>

#define LSEQ  65536
#define HID   512
#define OUTD  256
#define GATES 2048
#define KCAT  32
#define IIN   256
#define KCOMB 288
#define NBLK  128
#define CANARY 0xFFFA11EDu

// ---------------- scratch (static device globals; allocation-free) ----------
__device__ float g_gx[(size_t)LSEQ * GATES];     // 512 MB
__device__ float g_hs[(size_t)LSEQ * HID];       // 128 MB
__device__ float g_logits[(size_t)LSEQ * OUTD];  //  64 MB
__device__ float g_Wcomb[GATES * KCOMB];
__device__ float g_bt[GATES];

// ---------------- helpers ---------------------------------------------------
__device__ __forceinline__ float sig_f(float x) {
    float e = __expf(-x);              // x << 0 -> inf -> rcp -> 0
    return __frcp_rn(1.f + e);
}
__device__ __forceinline__ float tanh_f(float x) {
    float ax = fabsf(x);
    float e  = __expf(2.f * ax);       // overflow -> inf -> r -> 1
    float r  = 1.f - __fdividef(2.f, e + 1.f);
    return (x < 0.f) ? -r : r;
}
// .cv poll: empirically fastest poll flavor on this part
// (cv 107ms < cg 171 < volatile 195 < relaxed.gpu 245; DRAM=0.1% always).
__device__ __forceinline__ uint4 ldcv4(const uint4* p) {
    uint4 v;
    asm volatile("ld.global.cv.v4.u32 {%0,%1,%2,%3}, [%4];"
                 : "=r"(v.x), "=r"(v.y), "=r"(v.z), "=r"(v.w)
                 : "l"(p) : "memory");
    return v;
}
__device__ __forceinline__ void st_cg(float* p, float v) {
    asm volatile("st.global.cg.f32 [%0], %1;" :: "l"(p), "f"(v) : "memory");
}
__device__ __forceinline__ bool canary4(uint4 v) {
    return v.x == CANARY || v.y == CANARY || v.z == CANARY || v.w == CANARY;
}

// ---------------- poison g_hs with canary -----------------------------------
__global__ void poison_kernel(int n4) {
    uint4* dst = (uint4*)g_hs;
    uint4 v; v.x = CANARY; v.y = CANARY; v.z = CANARY; v.w = CANARY;
    for (int i = blockIdx.x * blockDim.x + threadIdx.x; i < n4;
         i += gridDim.x * blockDim.x)
        dst[i] = v;
}

// ---- W_comb = W_ih @ W_ctx ; b_tot = W_ih@b_ctx + b_ih + b_hh --------------
__global__ void wcomb_kernel(const float* __restrict__ Wih,
                             const float* __restrict__ Wctx,
                             const float* __restrict__ bctx,
                             const float* __restrict__ bih,
                             const float* __restrict__ bhh) {
    int r = blockIdx.x;          // 0..2047
    int j = threadIdx.x;         // 0..287
    float acc = 0.f;
#pragma unroll 8
    for (int k = 0; k < IIN; k++)
        acc = fmaf(__ldg(&Wih[r * IIN + k]), Wctx[k * KCOMB + j], acc);
    g_Wcomb[r * KCOMB + j] = acc;
    if (j == 0) {
        float a = bih[r] + bhh[r];
#pragma unroll 8
        for (int k = 0; k < IIN; k++)
            a = fmaf(Wih[r * IIN + k], bctx[k], a);
        g_bt[r] = a;
    }
}

// ---- tiled fp32 GEMM: C[M,N] = [A0|A1][M,c0+c1] @ B[N,K]^T + bias ----------
__global__ void __launch_bounds__(256)
gemm_tn(const float* __restrict__ A0, int c0,
        const float* __restrict__ A1, int c1,
        const float* __restrict__ B,
        const float* __restrict__ bias,
        float* __restrict__ C, int N) {
    const int K = c0 + c1;
    __shared__ float As[16][129];
    __shared__ float Bs[16][65];
    const int tid = threadIdx.x;
    const int m0 = blockIdx.y * 128;
    const int n0 = blockIdx.x * 64;
    const int tx = tid & 15;    // col group (4 cols)
    const int ty = tid >> 4;    // row group (8 rows)

    float acc[8][4];
#pragma unroll
    for (int i = 0; i < 8; i++)
#pragma unroll
        for (int j = 0; j < 4; j++) acc[i][j] = 0.f;

    for (int kt = 0; kt < K; kt += 16) {
#pragma unroll
        for (int i = 0; i < 8; i++) {
            int li = tid + i * 256;
            int m  = li >> 4;
            int kk = li & 15;
            int kg = kt + kk;
            float v;
            if (kg < c0) v = A0[(size_t)(m0 + m) * c0 + kg];
            else         v = A1[(size_t)(m0 + m) * c1 + (kg - c0)];
            As[kk][m] = v;
        }
#pragma unroll
        for (int i = 0; i < 4; i++) {
            int li = tid + i * 256;
            int n  = li >> 4;
            int kk = li & 15;
            Bs[kk][n] = B[(size_t)(n0 + n) * K + kt + kk];
        }
        __syncthreads();
#pragma unroll
        for (int kk = 0; kk < 16; kk++) {
            float a[8], b[4];
#pragma unroll
            for (int i = 0; i < 8; i++) a[i] = As[kk][ty * 8 + i];
#pragma unroll
            for (int j = 0; j < 4; j++) b[j] = Bs[kk][tx * 4 + j];
#pragma unroll
            for (int i = 0; i < 8; i++)
#pragma unroll
                for (int j = 0; j < 4; j++)
                    acc[i][j] = fmaf(a[i], b[j], acc[i][j]);
        }
        __syncthreads();
    }
#pragma unroll
    for (int i = 0; i < 8; i++) {
        int m = m0 + ty * 8 + i;
#pragma unroll
        for (int j = 0; j < 4; j++) {
            int n = n0 + tx * 4 + j;
            C[(size_t)m * N + n] = acc[i][j] + bias[n];
        }
    }
}

// ---- persistent LSTM recurrence --------------------------------------------
// 128 blocks x 256 threads, all co-resident. Block b owns hidden units
// 4b..4b+3 (16 gate rows). Cross-block h via g_hs: 4 scalar st.cg publishes;
// dual-slot software-pipelined ld.cv poll (two in-flight loads skewed ~300cy
// -> sampling cadence ~RT/2 instead of RT).
__global__ void __launch_bounds__(256, 1)
lstm_rec(const float* __restrict__ h0,
         const float* __restrict__ c0,
         const float* __restrict__ Whh,
         float* __restrict__ out_tail) {
    __shared__ float sh_h[512];
    __shared__ float sh_g[16];
    const int b    = blockIdx.x;
    const int tid  = threadIdx.x;
    const int lane = tid & 31;
    const int w    = tid >> 5;
    const int lg   = lane & 15;               // lane within 16-group
    const int rr   = w * 2 + (lane >> 4);     // 0..15: local gate row
    const int gi   = rr >> 2;                 // gate (i,f,g,o)
    const int jj   = rr & 3;                  // unit within block
    const int row  = gi * 512 + b * 4 + jj;   // global gate row

    // W_hh row resident in registers: element h-index = lg + 16*i
    float wreg[32];
#pragma unroll
    for (int i = 0; i < 32; i++)
        wreg[i] = Whh[(size_t)row * 512 + lg + 16 * i];

    float c_state = 0.f;
    if (tid < 4) c_state = c0[b * 4 + tid];
    float h_last = 0.f;

    // gx prefetch (depth 1): pull the DRAM load off the critical path
    float gx_cur = 0.f, gx_next = 0.f;
    if (lg == 0) gx_cur = __ldg(&g_gx[row]);

    for (int t = 0; t < LSEQ; t++) {
        // issue next step's gx load before the poll (latency overlap)
        if (lg == 0 && t + 1 < LSEQ)
            gx_next = __ldg(&g_gx[(size_t)(t + 1) * GATES + row]);

        // phase A: bring h_{t-1} into smem — dual-slot pipelined .cv poll
        if (tid < 128) {
            float4 hv;
            if (t == 0) {
                hv = ((const float4*)h0)[tid];
            } else {
                const uint4* p = (const uint4*)(g_hs + (size_t)(t - 1) * HID) + tid;
                uint4 sa = ldcv4(p);          // slot A in flight
                __nanosleep(150);             // ~300cy skew (overlaps A's flight)
                uint4 sb = ldcv4(p);          // slot B in flight, staggered
                uint4 u;
                int spin = 0;
                for (;;) {
                    if (!canary4(sa)) { u = sa; break; }   // sampled ~T+250+...
                    sa = ldcv4(p);                          // reissue A
                    if (!canary4(sb)) { u = sb; break; }   // sampled ~300 later
                    sb = ldcv4(p);                          // reissue B
                    if (++spin > 2048) __nanosleep(64);     // liveness guard
                }
                hv.x = __uint_as_float(u.x); hv.y = __uint_as_float(u.y);
                hv.z = __uint_as_float(u.z); hv.w = __uint_as_float(u.w);
            }
            ((float4*)sh_h)[tid] = hv;
        }
        __syncthreads();

        // phase B: 16 dot products, 4 independent accumulators per thread
        float a0 = 0.f, a1 = 0.f, a2 = 0.f, a3 = 0.f;
#pragma unroll
        for (int i = 0; i < 8; i++) {
            a0 = fmaf(wreg[4 * i + 0], sh_h[lg + 16 * (4 * i + 0)], a0);
            a1 = fmaf(wreg[4 * i + 1], sh_h[lg + 16 * (4 * i + 1)], a1);
            a2 = fmaf(wreg[4 * i + 2], sh_h[lg + 16 * (4 * i + 2)], a2);
            a3 = fmaf(wreg[4 * i + 3], sh_h[lg + 16 * (4 * i + 3)], a3);
        }
        float acc = (a0 + a1) + (a2 + a3);
#pragma unroll
        for (int off = 8; off; off >>= 1)
            acc += __shfl_xor_sync(0xffffffffu, acc, off);
        if (lg == 0) {
            float g = acc + gx_cur;
            sh_g[rr] = (gi == 2) ? tanh_f(g) : sig_f(g);  // parallel activations
        }
        __syncthreads();

        // phase C: combine + per-unit st.cg publish (R3-proven shape)
        if (tid < 4) {
            float ig = sh_g[tid];
            float fg = sh_g[4  + tid];
            float gg = sh_g[8  + tid];
            float og = sh_g[12 + tid];
            c_state  = fmaf(fg, c_state, ig * gg);
            float h  = og * tanh_f(c_state);
            h_last   = h;
            st_cg(&g_hs[(size_t)t * HID + b * 4 + tid], h);
        }
        gx_cur = gx_next;
    }
    if (tid < 4) {
        out_tail[b * 4 + tid]       = h_last;   // hn
        out_tail[HID + b * 4 + tid] = c_state;  // cn
    }
}

// ---- log-softmax: one warp per row of 256 ----------------------------------
__global__ void __launch_bounds__(256)
logsoftmax_kernel(float* __restrict__ out) {
    int row  = blockIdx.x * 8 + (threadIdx.x >> 5);
    int lane = threadIdx.x & 31;
    const float* x = g_logits + (size_t)row * OUTD;
    float v[8];
    float mx = -1e30f;
#pragma unroll
    for (int i = 0; i < 8; i++) { v[i] = x[lane + 32 * i]; mx = fmaxf(mx, v[i]); }
#pragma unroll
    for (int off = 16; off; off >>= 1)
        mx = fmaxf(mx, __shfl_xor_sync(0xffffffffu, mx, off));
    float s = 0.f;
#pragma unroll
    for (int i = 0; i < 8; i++) s += __expf(v[i] - mx);
#pragma unroll
    for (int off = 16; off; off >>= 1)
        s += __shfl_xor_sync(0xffffffffu, s, off);
    float lse = mx + __logf(s);
    float* o = out + (size_t)row * OUTD;
#pragma unroll
    for (int i = 0; i < 8; i++) o[lane + 32 * i] = v[i] - lse;
}

// ---------------- launch -----------------------------------------------------
extern "C" void kernel_launch(void* const* d_in, const int* in_sizes, int n_in,
                              void* d_out, int out_size) {
    const float* category = (const float*)d_in[0];
    const float* input    = (const float*)d_in[1];
    const float* hidden   = (const float*)d_in[2];
    const float* cell     = (const float*)d_in[3];
    const float* W_ctx    = (const float*)d_in[4];
    const float* b_ctx    = (const float*)d_in[5];
    const float* W_ih     = (const float*)d_in[6];
    const float* W_hh     = (const float*)d_in[7];
    const float* b_ih     = (const float*)d_in[8];
    const float* b_hh     = (const float*)d_in[9];
    const float* W_fc     = (const float*)d_in[10];
    const float* b_fc     = (const float*)d_in[11];
    float* out = (float*)d_out;

    float *p_gx = nullptr, *p_hs = nullptr, *p_logits = nullptr;
    float *p_wc = nullptr, *p_bt = nullptr;
    cudaGetSymbolAddress((void**)&p_gx,     g_gx);
    cudaGetSymbolAddress((void**)&p_hs,     g_hs);
    cudaGetSymbolAddress((void**)&p_logits, g_logits);
    cudaGetSymbolAddress((void**)&p_wc,     g_Wcomb);
    cudaGetSymbolAddress((void**)&p_bt,     g_bt);

    size_t main_elems = (size_t)LSEQ * OUTD;
    float* tail = ((size_t)out_size >= main_elems + 2 * HID)
                      ? out + main_elems
                      : p_logits;  // harmless scratch sink

    // 1. poison hs canaries (fresh every launch -> deterministic replays)
    poison_kernel<<<2048, 256>>>((int)((size_t)LSEQ * HID / 4));

    // 2. fold input projections
    wcomb_kernel<<<GATES, KCOMB>>>(W_ih, W_ctx, b_ctx, b_ih, b_hh);

    // 3. gx = [category|input] @ W_comb^T + b_tot
    gemm_tn<<<dim3(GATES / 64, LSEQ / 128), 256>>>(
        category, KCAT, input, IIN, p_wc, p_bt, p_gx, GATES);

    // 4. sequential recurrence (persistent, 128 blocks)
    lstm_rec<<<NBLK, 256>>>(hidden, cell, W_hh, tail);

    // 5. logits = hs @ W_fc^T + b_fc
    gemm_tn<<<dim3(OUTD / 64, LSEQ / 128), 256>>>(
        p_hs, HID, p_hs, 0, W_fc, b_fc, p_logits, OUTD);

    // 6. log-softmax -> d_out
    logsoftmax_kernel<<<LSEQ / 8, 256>>>(out);
}

// round 16
// speedup vs baseline: 2.1977x; 2.1977x over previous
#include <cuda_runtime.h>
#include <cuda_bf16.h>
#include <cstdint>
#include <cstddef>

#define LSEQ  65536
#define HID   512
#define OUTD  256
#define GATES 2048
#define KCAT  32
#define IIN   256
#define KCOMB 288
#define NBLK  128
#define CANARY 0xFFFA11EDu

// ---------------- scratch (static device globals; allocation-free) ----------
__device__ float g_gx[(size_t)LSEQ * GATES];     // 512 MB
__device__ float g_hs[(size_t)LSEQ * HID];       // 128 MB
__device__ float g_logits[(size_t)LSEQ * OUTD];  //  64 MB
__device__ float g_Wcomb[GATES * KCOMB];
__device__ float g_bt[GATES];

// ---------------- helpers ---------------------------------------------------
__device__ __forceinline__ float sig_f(float x) {
    float e = __expf(-x);              // x << 0 -> inf -> rcp -> 0
    return __frcp_rn(1.f + e);
}
__device__ __forceinline__ float tanh_f(float x) {
    float ax = fabsf(x);
    float e  = __expf(2.f * ax);       // overflow -> inf -> r -> 1
    float r  = 1.f - __fdividef(2.f, e + 1.f);
    return (x < 0.f) ? -r : r;
}
// .cv poll: empirically fastest poll flavor (cv 107ms < cg 171 < volatile 195
// < relaxed.gpu 245). Poll-side changes are exhausted; this round changes the
// PUBLISH side only.
__device__ __forceinline__ uint4 ldcv4(const uint4* p) {
    uint4 v;
    asm volatile("ld.global.cv.v4.u32 {%0,%1,%2,%3}, [%4];"
                 : "=r"(v.x), "=r"(v.y), "=r"(v.z), "=r"(v.w)
                 : "l"(p) : "memory");
    return v;
}

// ---------------- poison g_hs with canary -----------------------------------
__global__ void poison_kernel(int n4) {
    uint4* dst = (uint4*)g_hs;
    uint4 v; v.x = CANARY; v.y = CANARY; v.z = CANARY; v.w = CANARY;
    for (int i = blockIdx.x * blockDim.x + threadIdx.x; i < n4;
         i += gridDim.x * blockDim.x)
        dst[i] = v;
}

// ---- W_comb = W_ih @ W_ctx ; b_tot = W_ih@b_ctx + b_ih + b_hh --------------
__global__ void wcomb_kernel(const float* __restrict__ Wih,
                             const float* __restrict__ Wctx,
                             const float* __restrict__ bctx,
                             const float* __restrict__ bih,
                             const float* __restrict__ bhh) {
    int r = blockIdx.x;          // 0..2047
    int j = threadIdx.x;         // 0..287
    float acc = 0.f;
#pragma unroll 8
    for (int k = 0; k < IIN; k++)
        acc = fmaf(__ldg(&Wih[r * IIN + k]), Wctx[k * KCOMB + j], acc);
    g_Wcomb[r * KCOMB + j] = acc;
    if (j == 0) {
        float a = bih[r] + bhh[r];
#pragma unroll 8
        for (int k = 0; k < IIN; k++)
            a = fmaf(Wih[r * IIN + k], bctx[k], a);
        g_bt[r] = a;
    }
}

// ---- tiled fp32 GEMM: C[M,N] = [A0|A1][M,c0+c1] @ B[N,K]^T + bias ----------
__global__ void __launch_bounds__(256)
gemm_tn(const float* __restrict__ A0, int c0,
        const float* __restrict__ A1, int c1,
        const float* __restrict__ B,
        const float* __restrict__ bias,
        float* __restrict__ C, int N) {
    const int K = c0 + c1;
    __shared__ float As[16][129];
    __shared__ float Bs[16][65];
    const int tid = threadIdx.x;
    const int m0 = blockIdx.y * 128;
    const int n0 = blockIdx.x * 64;
    const int tx = tid & 15;    // col group (4 cols)
    const int ty = tid >> 4;    // row group (8 rows)

    float acc[8][4];
#pragma unroll
    for (int i = 0; i < 8; i++)
#pragma unroll
        for (int j = 0; j < 4; j++) acc[i][j] = 0.f;

    for (int kt = 0; kt < K; kt += 16) {
#pragma unroll
        for (int i = 0; i < 8; i++) {
            int li = tid + i * 256;
            int m  = li >> 4;
            int kk = li & 15;
            int kg = kt + kk;
            float v;
            if (kg < c0) v = A0[(size_t)(m0 + m) * c0 + kg];
            else         v = A1[(size_t)(m0 + m) * c1 + (kg - c0)];
            As[kk][m] = v;
        }
#pragma unroll
        for (int i = 0; i < 4; i++) {
            int li = tid + i * 256;
            int n  = li >> 4;
            int kk = li & 15;
            Bs[kk][n] = B[(size_t)(n0 + n) * K + kt + kk];
        }
        __syncthreads();
#pragma unroll
        for (int kk = 0; kk < 16; kk++) {
            float a[8], b[4];
#pragma unroll
            for (int i = 0; i < 8; i++) a[i] = As[kk][ty * 8 + i];
#pragma unroll
            for (int j = 0; j < 4; j++) b[j] = Bs[kk][tx * 4 + j];
#pragma unroll
            for (int i = 0; i < 8; i++)
#pragma unroll
                for (int j = 0; j < 4; j++)
                    acc[i][j] = fmaf(a[i], b[j], acc[i][j]);
        }
        __syncthreads();
    }
#pragma unroll
    for (int i = 0; i < 8; i++) {
        int m = m0 + ty * 8 + i;
#pragma unroll
        for (int j = 0; j < 4; j++) {
            int n = n0 + tx * 4 + j;
            C[(size_t)m * N + n] = acc[i][j] + bias[n];
        }
    }
}

// ---- persistent LSTM recurrence --------------------------------------------
// 128 blocks x 256 threads, all co-resident. Block b owns hidden units
// 4b..4b+3 (16 gate rows). Cross-block h through g_hs. SINGLE-VARIABLE CHANGE
// vs the 107ms baseline: publish via atomicExch (LTS-processed, immediately
// globally observable) instead of st.cg (write-path visibility delay).
// Poll: exact R3 tight ld.cv loop.
__global__ void __launch_bounds__(256, 1)
lstm_rec(const float* __restrict__ h0,
         const float* __restrict__ c0,
         const float* __restrict__ Whh,
         float* __restrict__ out_tail) {
    __shared__ float sh_h[512];
    __shared__ float sh_g[16];
    const int b    = blockIdx.x;
    const int tid  = threadIdx.x;
    const int lane = tid & 31;
    const int w    = tid >> 5;
    const int lg   = lane & 15;               // lane within 16-group
    const int rr   = w * 2 + (lane >> 4);     // 0..15: local gate row
    const int gi   = rr >> 2;                 // gate (i,f,g,o)
    const int jj   = rr & 3;                  // unit within block
    const int row  = gi * 512 + b * 4 + jj;   // global gate row

    // W_hh row resident in registers: element h-index = lg + 16*i
    float wreg[32];
#pragma unroll
    for (int i = 0; i < 32; i++)
        wreg[i] = Whh[(size_t)row * 512 + lg + 16 * i];

    float c_state = 0.f;
    if (tid < 4) c_state = c0[b * 4 + tid];
    float h_last = 0.f;

    // gx prefetch (depth 1): pull the DRAM load off the critical path
    float gx_cur = 0.f, gx_next = 0.f;
    if (lg == 0) gx_cur = __ldg(&g_gx[row]);

    for (int t = 0; t < LSEQ; t++) {
        // issue next step's gx load before the poll (latency overlap)
        if (lg == 0 && t + 1 < LSEQ)
            gx_next = __ldg(&g_gx[(size_t)(t + 1) * GATES + row]);

        // phase A: bring h_{t-1} into smem (exact R3 tight .cv poll)
        if (tid < 128) {
            float4 hv;
            if (t == 0) {
                hv = ((const float4*)h0)[tid];
            } else {
                const uint4* p = (const uint4*)(g_hs + (size_t)(t - 1) * HID) + tid;
                uint4 u = ldcv4(p);
                while (u.x == CANARY || u.y == CANARY ||
                       u.z == CANARY || u.w == CANARY) {
                    __nanosleep(32);
                    u = ldcv4(p);
                }
                hv.x = __uint_as_float(u.x); hv.y = __uint_as_float(u.y);
                hv.z = __uint_as_float(u.z); hv.w = __uint_as_float(u.w);
            }
            ((float4*)sh_h)[tid] = hv;
        }
        __syncthreads();

        // phase B: 16 dot products, 4 independent accumulators per thread
        float a0 = 0.f, a1 = 0.f, a2 = 0.f, a3 = 0.f;
#pragma unroll
        for (int i = 0; i < 8; i++) {
            a0 = fmaf(wreg[4 * i + 0], sh_h[lg + 16 * (4 * i + 0)], a0);
            a1 = fmaf(wreg[4 * i + 1], sh_h[lg + 16 * (4 * i + 1)], a1);
            a2 = fmaf(wreg[4 * i + 2], sh_h[lg + 16 * (4 * i + 2)], a2);
            a3 = fmaf(wreg[4 * i + 3], sh_h[lg + 16 * (4 * i + 3)], a3);
        }
        float acc = (a0 + a1) + (a2 + a3);
#pragma unroll
        for (int off = 8; off; off >>= 1)
            acc += __shfl_xor_sync(0xffffffffu, acc, off);
        if (lg == 0) {
            float g = acc + gx_cur;
            sh_g[rr] = (gi == 2) ? tanh_f(g) : sig_f(g);  // parallel activations
        }
        __syncthreads();

        // phase C: combine + ATOMIC publish (fire-and-forget; LTS-visible
        // immediately, unlike st.cg's write-path delay)
        if (tid < 4) {
            float ig = sh_g[tid];
            float fg = sh_g[4  + tid];
            float gg = sh_g[8  + tid];
            float og = sh_g[12 + tid];
            c_state  = fmaf(fg, c_state, ig * gg);
            float h  = og * tanh_f(c_state);
            h_last   = h;
            atomicExch((unsigned int*)&g_hs[(size_t)t * HID + b * 4 + tid],
                       __float_as_uint(h));
        }
        gx_cur = gx_next;
    }
    if (tid < 4) {
        out_tail[b * 4 + tid]       = h_last;   // hn
        out_tail[HID + b * 4 + tid] = c_state;  // cn
    }
}

// ---- log-softmax: one warp per row of 256 ----------------------------------
__global__ void __launch_bounds__(256)
logsoftmax_kernel(float* __restrict__ out) {
    int row  = blockIdx.x * 8 + (threadIdx.x >> 5);
    int lane = threadIdx.x & 31;
    const float* x = g_logits + (size_t)row * OUTD;
    float v[8];
    float mx = -1e30f;
#pragma unroll
    for (int i = 0; i < 8; i++) { v[i] = x[lane + 32 * i]; mx = fmaxf(mx, v[i]); }
#pragma unroll
    for (int off = 16; off; off >>= 1)
        mx = fmaxf(mx, __shfl_xor_sync(0xffffffffu, mx, off));
    float s = 0.f;
#pragma unroll
    for (int i = 0; i < 8; i++) s += __expf(v[i] - mx);
#pragma unroll
    for (int off = 16; off; off >>= 1)
        s += __shfl_xor_sync(0xffffffffu, s, off);
    float lse = mx + __logf(s);
    float* o = out + (size_t)row * OUTD;
#pragma unroll
    for (int i = 0; i < 8; i++) o[lane + 32 * i] = v[i] - lse;
}

// ---------------- launch -----------------------------------------------------
extern "C" void kernel_launch(void* const* d_in, const int* in_sizes, int n_in,
                              void* d_out, int out_size) {
    const float* category = (const float*)d_in[0];
    const float* input    = (const float*)d_in[1];
    const float* hidden   = (const float*)d_in[2];
    const float* cell     = (const float*)d_in[3];
    const float* W_ctx    = (const float*)d_in[4];
    const float* b_ctx    = (const float*)d_in[5];
    const float* W_ih     = (const float*)d_in[6];
    const float* W_hh     = (const float*)d_in[7];
    const float* b_ih     = (const float*)d_in[8];
    const float* b_hh     = (const float*)d_in[9];
    const float* W_fc     = (const float*)d_in[10];
    const float* b_fc     = (const float*)d_in[11];
    float* out = (float*)d_out;

    float *p_gx = nullptr, *p_hs = nullptr, *p_logits = nullptr;
    float *p_wc = nullptr, *p_bt = nullptr;
    cudaGetSymbolAddress((void**)&p_gx,     g_gx);
    cudaGetSymbolAddress((void**)&p_hs,     g_hs);
    cudaGetSymbolAddress((void**)&p_logits, g_logits);
    cudaGetSymbolAddress((void**)&p_wc,     g_Wcomb);
    cudaGetSymbolAddress((void**)&p_bt,     g_bt);

    size_t main_elems = (size_t)LSEQ * OUTD;
    float* tail = ((size_t)out_size >= main_elems + 2 * HID)
                      ? out + main_elems
                      : p_logits;  // harmless scratch sink

    // 1. poison hs canaries (fresh every launch -> deterministic replays)
    poison_kernel<<<2048, 256>>>((int)((size_t)LSEQ * HID / 4));

    // 2. fold input projections
    wcomb_kernel<<<GATES, KCOMB>>>(W_ih, W_ctx, b_ctx, b_ih, b_hh);

    // 3. gx = [category|input] @ W_comb^T + b_tot
    gemm_tn<<<dim3(GATES / 64, LSEQ / 128), 256>>>(
        category, KCAT, input, IIN, p_wc, p_bt, p_gx, GATES);

    // 4. sequential recurrence (persistent, 128 blocks)
    lstm_rec<<<NBLK, 256>>>(hidden, cell, W_hh, tail);

    // 5. logits = hs @ W_fc^T + b_fc
    gemm_tn<<<dim3(OUTD / 64, LSEQ / 128), 256>>>(
        p_hs, HID, p_hs, 0, W_fc, b_fc, p_logits, OUTD);

    // 6. log-softmax -> d_out
    logsoftmax_kernel<<<LSEQ / 8, 256>>>(out);
}